// round 16
// baseline (speedup 1.0000x reference)
#include <cuda_runtime.h>
#include <math.h>

// ---------------- Problem constants ----------------
#define BB   2
#define TT   4
#define HWN  1024            // H*W
#define TKV  4096            // T*H*W
#define DQ   768             // DINO_DIM
#define CK   1920            // COG_DIM
#define NH   12
#define HD   64
#define MQ   (BB*HWN)        // 2048 query rows
#define MKV  (BB*TKV)        // 8192 kv rows

typedef unsigned long long ull;

// ---------------- packed fp32x2 helpers (sm_100+ dual-FP32 pipe) ----------------
__device__ __forceinline__ void ffma2(ull &d, ull a, ull b) {
    asm("fma.rn.f32x2 %0, %1, %2, %0;" : "+l"(d) : "l"(a), "l"(b));
}
__device__ __forceinline__ void mul2(ull &d, ull a) {
    asm("mul.rn.f32x2 %0, %0, %1;" : "+l"(d) : "l"(a));
}
__device__ __forceinline__ ull dup2(float x) {
    ull r; asm("mov.b64 %0, {%1, %1};" : "=l"(r) : "f"(x)); return r;
}
__device__ __forceinline__ ull pack2(float x, float y) {
    ull r; asm("mov.b64 %0, {%1, %2};" : "=l"(r) : "f"(x), "f"(y)); return r;
}
__device__ __forceinline__ float2 unpack2(ull v) {
    float2 f; asm("mov.b64 {%0, %1}, %2;" : "=f"(f.x), "=f"(f.y) : "l"(v)); return f;
}

// ---------------- Scratch (device globals; no allocation APIs) ----------------
__device__ float g_xq [MQ  * DQ];
__device__ float g_xkv[MKV * CK];
__device__ float g_q  [MQ  * DQ];
__device__ float g_k  [MKV * DQ];
__device__ float g_v  [MKV * DQ];
__device__ float g_att[MQ  * DQ];

// ---------------- LayerNorm q path: input [B, 768, 32, 32] (strided channels) ----------------
__global__ __launch_bounds__(256) void ln_q_kernel(const float* __restrict__ x,
                                                   const float* __restrict__ g,
                                                   const float* __restrict__ be)
{
    int row = blockIdx.x;            // b*1024 + pix
    int b   = row >> 10;
    int pix = row & 1023;
    const float* base = x + (size_t)b * DQ * HWN + pix;

    __shared__ float sbuf[DQ];
    __shared__ float red[256];
    int tid = threadIdx.x;

    float s = 0.f;
    for (int c = tid; c < DQ; c += 256) {
        float v = base[(size_t)c * HWN];
        sbuf[c] = v;
        s += v;
    }
    red[tid] = s; __syncthreads();
    for (int st = 128; st > 0; st >>= 1) { if (tid < st) red[tid] += red[tid + st]; __syncthreads(); }
    float mu = red[0] * (1.f / DQ);
    __syncthreads();

    float s2 = 0.f;
    for (int c = tid; c < DQ; c += 256) { float d = sbuf[c] - mu; s2 += d * d; }
    red[tid] = s2; __syncthreads();
    for (int st = 128; st > 0; st >>= 1) { if (tid < st) red[tid] += red[tid + st]; __syncthreads(); }
    float rstd = rsqrtf(red[0] * (1.f / DQ) + 1e-5f);

    float* out = g_xq + (size_t)row * DQ;
    for (int c = tid; c < DQ; c += 256)
        out[c] = (sbuf[c] - mu) * rstd * g[c] + be[c];
}

// ---------------- LayerNorm kv path: input [B,T,H,W,1920], float4 ----------------
__global__ __launch_bounds__(256) void ln_kv_kernel(const float* __restrict__ x,
                                                    const float* __restrict__ g,
                                                    const float* __restrict__ be)
{
    int row = blockIdx.x;            // 0..8191
    const float4* base = (const float4*)(x + (size_t)row * CK);
    const float4* g4   = (const float4*)g;
    const float4* be4  = (const float4*)be;

    __shared__ float4 sbuf[CK / 4];  // 480
    __shared__ float red[256];
    int tid = threadIdx.x;

    float s = 0.f;
    for (int c = tid; c < CK / 4; c += 256) {
        float4 v = base[c];
        sbuf[c] = v;
        s += v.x + v.y + v.z + v.w;
    }
    red[tid] = s; __syncthreads();
    for (int st = 128; st > 0; st >>= 1) { if (tid < st) red[tid] += red[tid + st]; __syncthreads(); }
    float mu = red[0] * (1.f / CK);
    __syncthreads();

    float s2 = 0.f;
    for (int c = tid; c < CK / 4; c += 256) {
        float4 v = sbuf[c];
        float dx = v.x - mu, dy = v.y - mu, dz = v.z - mu, dw = v.w - mu;
        s2 += dx * dx + dy * dy + dz * dz + dw * dw;
    }
    red[tid] = s2; __syncthreads();
    for (int st = 128; st > 0; st >>= 1) { if (tid < st) red[tid] += red[tid + st]; __syncthreads(); }
    float rstd = rsqrtf(red[0] * (1.f / CK) + 1e-5f);

    float4* out = (float4*)(g_xkv + (size_t)row * CK);
    for (int c = tid; c < CK / 4; c += 256) {
        float4 v = sbuf[c], gv = g4[c], bv = be4[c];
        float4 o;
        o.x = (v.x - mu) * rstd * gv.x + bv.x;
        o.y = (v.y - mu) * rstd * gv.y + bv.y;
        o.z = (v.z - mu) * rstd * gv.z + bv.z;
        o.w = (v.w - mu) * rstd * gv.w + bv.w;
        out[c] = o;
    }
}

// ---------------- SGEMM: 128x128x16 tile, double-buffered, ffma2, 2 CTAs/SM ----------------
__global__ __launch_bounds__(256, 2) void gemm128(const float* __restrict__ A, int lda,
                                                  const float* __restrict__ Bw, int ldb,
                                                  const float* __restrict__ bias,
                                                  float* __restrict__ C, int ldc,
                                                  int K, int outMode)
{
    __shared__ float As[2][16][128];
    __shared__ float Bs[2][16][128];

    int tid = threadIdx.x;
    int bm = blockIdx.y * 128;
    int bn = blockIdx.x * 128;
    int tx = tid & 15, ty = tid >> 4;

    int ar = tid >> 1;            // 0..127
    int ac = (tid & 1) * 8;       // 0 or 8
    int br = tid >> 4;            // 0..15
    int bc = (tid & 15) * 4;      // 0..60

    const float* Ap = A + (size_t)(bm + ar) * lda + ac;
    const float* Bp = Bw + (size_t)br * ldb + bn + bc;

    ull acc[8][4];
#pragma unroll
    for (int i = 0; i < 8; i++)
#pragma unroll
        for (int j = 0; j < 4; j++) acc[i][j] = 0ULL;

    int nt = K >> 4;

    float4 av0 = *(const float4*)(Ap);
    float4 av1 = *(const float4*)(Ap + 4);
    float4 bv0 = *(const float4*)(Bp);
    float4 bv1 = *(const float4*)(Bp + 64);
    As[0][ac + 0][ar] = av0.x; As[0][ac + 1][ar] = av0.y;
    As[0][ac + 2][ar] = av0.z; As[0][ac + 3][ar] = av0.w;
    As[0][ac + 4][ar] = av1.x; As[0][ac + 5][ar] = av1.y;
    As[0][ac + 6][ar] = av1.z; As[0][ac + 7][ar] = av1.w;
    *(float4*)&Bs[0][br][bc]      = bv0;
    *(float4*)&Bs[0][br][bc + 64] = bv1;
    __syncthreads();

    for (int t = 0; t < nt; t++) {
        int cur = t & 1;
        if (t + 1 < nt) {
            const float* Ap2 = Ap + (t + 1) * 16;
            const float* Bp2 = Bp + (size_t)(t + 1) * 16 * ldb;
            av0 = *(const float4*)(Ap2);
            av1 = *(const float4*)(Ap2 + 4);
            bv0 = *(const float4*)(Bp2);
            bv1 = *(const float4*)(Bp2 + 64);
        }

#pragma unroll
        for (int kk = 0; kk < 16; kk++) {
            float4 a0 = *(const float4*)&As[cur][kk][ty * 4];
            float4 a1 = *(const float4*)&As[cur][kk][64 + ty * 4];
            float4 b0 = *(const float4*)&Bs[cur][kk][tx * 4];
            float4 b1 = *(const float4*)&Bs[cur][kk][64 + tx * 4];
            ull bd0 = pack2(b0.x, b0.y), bd1 = pack2(b0.z, b0.w);
            ull bd2 = pack2(b1.x, b1.y), bd3 = pack2(b1.z, b1.w);
            ull ad[8] = { dup2(a0.x), dup2(a0.y), dup2(a0.z), dup2(a0.w),
                          dup2(a1.x), dup2(a1.y), dup2(a1.z), dup2(a1.w) };
#pragma unroll
            for (int i = 0; i < 8; i++) {
                ffma2(acc[i][0], ad[i], bd0);
                ffma2(acc[i][1], ad[i], bd1);
                ffma2(acc[i][2], ad[i], bd2);
                ffma2(acc[i][3], ad[i], bd3);
            }
        }

        if (t + 1 < nt) {
            int nxt = cur ^ 1;
            As[nxt][ac + 0][ar] = av0.x; As[nxt][ac + 1][ar] = av0.y;
            As[nxt][ac + 2][ar] = av0.z; As[nxt][ac + 3][ar] = av0.w;
            As[nxt][ac + 4][ar] = av1.x; As[nxt][ac + 5][ar] = av1.y;
            As[nxt][ac + 6][ar] = av1.z; As[nxt][ac + 7][ar] = av1.w;
            *(float4*)&Bs[nxt][br][bc]      = bv0;
            *(float4*)&Bs[nxt][br][bc + 64] = bv1;
        }
        __syncthreads();
    }

    int n0 = bn + tx * 4;
    float4 bb0 = *(const float4*)&bias[n0];
    float4 bb1 = *(const float4*)&bias[n0 + 64];
#pragma unroll
    for (int i = 0; i < 8; i++) {
        int m = bm + ((i < 4) ? (ty * 4 + i) : (64 + ty * 4 + (i - 4)));
        float2 p0 = unpack2(acc[i][0]), p1 = unpack2(acc[i][1]);
        float2 p2 = unpack2(acc[i][2]), p3 = unpack2(acc[i][3]);
        float4 o0 = make_float4(p0.x + bb0.x, p0.y + bb0.y, p1.x + bb0.z, p1.y + bb0.w);
        float4 o1 = make_float4(p2.x + bb1.x, p2.y + bb1.y, p3.x + bb1.z, p3.y + bb1.w);
        if (outMode == 0) {
            *(float4*)&C[(size_t)m * ldc + n0]      = o0;
            *(float4*)&C[(size_t)m * ldc + n0 + 64] = o1;
        } else {
            int b   = m >> 10;
            int pix = m & 1023;
            size_t base = (size_t)b * DQ * HWN + pix;
            C[base + (size_t)(n0 + 0) * HWN] = o0.x;
            C[base + (size_t)(n0 + 1) * HWN] = o0.y;
            C[base + (size_t)(n0 + 2) * HWN] = o0.z;
            C[base + (size_t)(n0 + 3) * HWN] = o0.w;
            C[base + (size_t)(n0 + 64) * HWN] = o1.x;
            C[base + (size_t)(n0 + 65) * HWN] = o1.y;
            C[base + (size_t)(n0 + 66) * HWN] = o1.z;
            C[base + (size_t)(n0 + 67) * HWN] = o1.w;
        }
    }
}

// ---------------- Fused flash attention: S=QK^T, online softmax, O=PV ----------------
// grid (HW/64, B*NH), 256 threads. Per block: 64 query rows, full K sweep in 64-key tiles.
// No score tensor in HBM. Temporal weight constant per 64-key tile (1024 keys/frame).
#define LD   68   // smem row pitch (floats)
__global__ __launch_bounds__(256, 2) void flash_kernel(const float* __restrict__ tw)
{
    extern __shared__ float sm[];
    float* Qs = sm;                  // [64][LD]
    float* Ks = sm + 64 * LD;        // [64][LD]
    float* Vs = sm + 2 * 64 * LD;    // [64][LD]
    float* Ps = sm + 3 * 64 * LD;    // [64][LD]

    int bh = blockIdx.y;
    int b  = bh / NH;
    int h  = bh % NH;
    int qm0 = blockIdx.x * 64;

    int tid = threadIdx.x;
    int tx = tid & 15, ty = tid >> 4;

    // Load Q tile (64 rows x 64 dims of head h)
    {
        int r  = tid >> 2;            // 0..63
        int c0 = (tid & 3) * 16;      // 0,16,32,48
        const float* qsrc = g_q + (size_t)(b * HWN + qm0 + r) * DQ + h * HD + c0;
#pragma unroll
        for (int j = 0; j < 4; j++)
            *(float4*)&Qs[r * LD + c0 + 4 * j] = *(const float4*)(qsrc + 4 * j);
    }

    ull   o_acc[4][2];
    float m_i[4], l_i[4];
#pragma unroll
    for (int i = 0; i < 4; i++) {
        o_acc[i][0] = 0ULL; o_acc[i][1] = 0ULL;
        m_i[i] = -1e30f; l_i[i] = 0.f;
    }

    const float* kbase = g_k + (size_t)b * TKV * DQ + h * HD;
    const float* vbase = g_v + (size_t)b * TKV * DQ + h * HD;

    for (int kt = 0; kt < TKV / 64; kt++) {
        int kn0 = kt * 64;
        // Load K,V tiles (64 keys x 64 dims)
        {
            int r  = tid >> 2;
            int c0 = (tid & 3) * 16;
            const float* ksrc = kbase + (size_t)(kn0 + r) * DQ + c0;
            const float* vsrc = vbase + (size_t)(kn0 + r) * DQ + c0;
#pragma unroll
            for (int j = 0; j < 4; j++) {
                *(float4*)&Ks[r * LD + c0 + 4 * j] = *(const float4*)(ksrc + 4 * j);
                *(float4*)&Vs[r * LD + c0 + 4 * j] = *(const float4*)(vsrc + 4 * j);
            }
        }
        __syncthreads();

        // ---- S = Q K^T (4x4 per thread), packed over d pairs ----
        ull sacc[4][4];
#pragma unroll
        for (int i = 0; i < 4; i++)
#pragma unroll
            for (int j = 0; j < 4; j++) sacc[i][j] = 0ULL;

#pragma unroll 4
        for (int k4 = 0; k4 < 64; k4 += 4) {
            ull a2[4][2], b2[4][2];
#pragma unroll
            for (int i = 0; i < 4; i++) {
                float4 q = *(const float4*)&Qs[(ty * 4 + i) * LD + k4];
                a2[i][0] = pack2(q.x, q.y);
                a2[i][1] = pack2(q.z, q.w);
            }
#pragma unroll
            for (int j = 0; j < 4; j++) {
                float4 kv = *(const float4*)&Ks[(tx * 4 + j) * LD + k4];
                b2[j][0] = pack2(kv.x, kv.y);
                b2[j][1] = pack2(kv.z, kv.w);
            }
#pragma unroll
            for (int i = 0; i < 4; i++)
#pragma unroll
                for (int j = 0; j < 4; j++) {
                    ffma2(sacc[i][j], a2[i][0], b2[j][0]);
                    ffma2(sacc[i][j], a2[i][1], b2[j][1]);
                }
        }

        float scale = 0.125f * tw[kn0 >> 10];
        float s[4][4];
#pragma unroll
        for (int i = 0; i < 4; i++)
#pragma unroll
            for (int j = 0; j < 4; j++) {
                float2 p = unpack2(sacc[i][j]);
                s[i][j] = (p.x + p.y) * scale;
            }

        // ---- online softmax: row stats over 16 tx lanes ----
#pragma unroll
        for (int i = 0; i < 4; i++) {
            float mt = fmaxf(fmaxf(s[i][0], s[i][1]), fmaxf(s[i][2], s[i][3]));
#pragma unroll
            for (int m = 1; m < 16; m <<= 1)
                mt = fmaxf(mt, __shfl_xor_sync(0xffffffffu, mt, m));
            float m_new = fmaxf(m_i[i], mt);
            float corr  = __expf(m_i[i] - m_new);
            float rs = 0.f;
#pragma unroll
            for (int j = 0; j < 4; j++) {
                float p = __expf(s[i][j] - m_new);
                s[i][j] = p;
                rs += p;
            }
#pragma unroll
            for (int m = 1; m < 16; m <<= 1)
                rs += __shfl_xor_sync(0xffffffffu, rs, m);
            l_i[i] = l_i[i] * corr + rs;
            m_i[i] = m_new;
            ull cc = dup2(corr);
            mul2(o_acc[i][0], cc);
            mul2(o_acc[i][1], cc);
        }

        // ---- stage P, then O += P V ----
#pragma unroll
        for (int i = 0; i < 4; i++)
            *(float4*)&Ps[(ty * 4 + i) * LD + tx * 4] =
                make_float4(s[i][0], s[i][1], s[i][2], s[i][3]);
        __syncthreads();

#pragma unroll 4
        for (int kk = 0; kk < 64; kk++) {
            float4 vr = *(const float4*)&Vs[kk * LD + tx * 4];
            ull b0 = pack2(vr.x, vr.y), b1 = pack2(vr.z, vr.w);
#pragma unroll
            for (int i = 0; i < 4; i++) {
                ull a = dup2(Ps[(ty * 4 + i) * LD + kk]);
                ffma2(o_acc[i][0], a, b0);
                ffma2(o_acc[i][1], a, b1);
            }
        }
        __syncthreads();
    }

    // ---- epilogue: O / l ----
#pragma unroll
    for (int i = 0; i < 4; i++) {
        float inv = 1.f / l_i[i];
        float2 r0 = unpack2(o_acc[i][0]), r1 = unpack2(o_acc[i][1]);
        float4 o = make_float4(r0.x * inv, r0.y * inv, r1.x * inv, r1.y * inv);
        *(float4*)&g_att[((size_t)(b * HWN + qm0 + ty * 4 + i)) * DQ + h * HD + tx * 4] = o;
    }
}

#define FLASH_SMEM (4 * 64 * LD * 4)   // 69,632 bytes

// ---------------- Launch ----------------
extern "C" void kernel_launch(void* const* d_in, const int* in_sizes, int n_in,
                              void* d_out, int out_size)
{
    const float* dino = (const float*)d_in[0];
    const float* cog  = (const float*)d_in[1];
    const float* tw   = (const float*)d_in[2];
    const float* Wq   = (const float*)d_in[3];
    const float* bq   = (const float*)d_in[4];
    const float* Wk   = (const float*)d_in[5];
    const float* bk   = (const float*)d_in[6];
    const float* Wv   = (const float*)d_in[7];
    const float* bv   = (const float*)d_in[8];
    const float* Wo   = (const float*)d_in[9];
    const float* bo   = (const float*)d_in[10];
    const float* gq   = (const float*)d_in[11];
    const float* Bq   = (const float*)d_in[12];
    const float* gkv  = (const float*)d_in[13];
    const float* Bkv  = (const float*)d_in[14];
    float* out = (float*)d_out;

    float *p_xq, *p_xkv, *p_q, *p_k, *p_v, *p_att;
    cudaGetSymbolAddress((void**)&p_xq,  g_xq);
    cudaGetSymbolAddress((void**)&p_xkv, g_xkv);
    cudaGetSymbolAddress((void**)&p_q,   g_q);
    cudaGetSymbolAddress((void**)&p_k,   g_k);
    cudaGetSymbolAddress((void**)&p_v,   g_v);
    cudaGetSymbolAddress((void**)&p_att, g_att);

    cudaFuncSetAttribute(flash_kernel, cudaFuncAttributeMaxDynamicSharedMemorySize, FLASH_SMEM);

    // 1. LayerNorms
    ln_q_kernel <<<MQ,  256>>>(dino, gq,  Bq);
    ln_kv_kernel<<<MKV, 256>>>(cog,  gkv, Bkv);

    // 2. Projections
    gemm128<<<dim3(DQ/128, MQ/128),  256>>>(p_xq,  DQ, Wq, DQ, bq, p_q, DQ, DQ, 0);
    gemm128<<<dim3(DQ/128, MKV/128), 256>>>(p_xkv, CK, Wk, DQ, bk, p_k, DQ, CK, 0);
    gemm128<<<dim3(DQ/128, MKV/128), 256>>>(p_xkv, CK, Wv, DQ, bv, p_v, DQ, CK, 0);

    // 3. Fused attention (scores + softmax + PV)
    flash_kernel<<<dim3(HWN/64, BB*NH), 256, FLASH_SMEM>>>(tw);

    // 4. Output projection with fused BCHW transpose
    gemm128<<<dim3(DQ/128, MQ/128), 256>>>(p_att, DQ, Wo, DQ, bo, out, DQ, DQ, 1);
}

// round 17
// speedup vs baseline: 1.0023x; 1.0023x over previous
#include <cuda_runtime.h>
#include <math.h>

// ---------------- Problem constants ----------------
#define BB   2
#define TT   4
#define HWN  1024            // H*W
#define TKV  4096            // T*H*W
#define DQ   768             // DINO_DIM
#define CK   1920            // COG_DIM
#define NH   12
#define HD   64
#define MQ   (BB*HWN)        // 2048 query rows
#define MKV  (BB*TKV)        // 8192 kv rows

typedef unsigned long long ull;

// ---------------- packed fp32x2 helpers (sm_100+ dual-FP32 pipe) ----------------
__device__ __forceinline__ void ffma2(ull &d, ull a, ull b) {
    asm("fma.rn.f32x2 %0, %1, %2, %0;" : "+l"(d) : "l"(a), "l"(b));
}
__device__ __forceinline__ void mul2(ull &d, ull a) {
    asm("mul.rn.f32x2 %0, %0, %1;" : "+l"(d) : "l"(a));
}
__device__ __forceinline__ ull dup2(float x) {
    ull r; asm("mov.b64 %0, {%1, %1};" : "=l"(r) : "f"(x)); return r;
}
__device__ __forceinline__ ull pack2(float x, float y) {
    ull r; asm("mov.b64 %0, {%1, %2};" : "=l"(r) : "f"(x), "f"(y)); return r;
}
__device__ __forceinline__ float2 unpack2(ull v) {
    float2 f; asm("mov.b64 {%0, %1}, %2;" : "=f"(f.x), "=f"(f.y) : "l"(v)); return f;
}

// ---------------- Scratch (device globals; no allocation APIs) ----------------
__device__ float g_xq [MQ  * DQ];
__device__ float g_xkv[MKV * CK];
__device__ float g_q  [MQ  * DQ];
__device__ float g_k  [MKV * DQ];
__device__ float g_v  [MKV * DQ];
__device__ float g_att[MQ  * DQ];

// ---------------- LayerNorm q path: input [B, 768, 32, 32] (strided channels) ----------------
__global__ __launch_bounds__(256) void ln_q_kernel(const float* __restrict__ x,
                                                   const float* __restrict__ g,
                                                   const float* __restrict__ be)
{
    int row = blockIdx.x;            // b*1024 + pix
    int b   = row >> 10;
    int pix = row & 1023;
    const float* base = x + (size_t)b * DQ * HWN + pix;

    __shared__ float sbuf[DQ];
    __shared__ float red[256];
    int tid = threadIdx.x;

    float s = 0.f;
    for (int c = tid; c < DQ; c += 256) {
        float v = base[(size_t)c * HWN];
        sbuf[c] = v;
        s += v;
    }
    red[tid] = s; __syncthreads();
    for (int st = 128; st > 0; st >>= 1) { if (tid < st) red[tid] += red[tid + st]; __syncthreads(); }
    float mu = red[0] * (1.f / DQ);
    __syncthreads();

    float s2 = 0.f;
    for (int c = tid; c < DQ; c += 256) { float d = sbuf[c] - mu; s2 += d * d; }
    red[tid] = s2; __syncthreads();
    for (int st = 128; st > 0; st >>= 1) { if (tid < st) red[tid] += red[tid + st]; __syncthreads(); }
    float rstd = rsqrtf(red[0] * (1.f / DQ) + 1e-5f);

    float* out = g_xq + (size_t)row * DQ;
    for (int c = tid; c < DQ; c += 256)
        out[c] = (sbuf[c] - mu) * rstd * g[c] + be[c];
}

// ---------------- LayerNorm kv path: input [B,T,H,W,1920], float4 ----------------
__global__ __launch_bounds__(256) void ln_kv_kernel(const float* __restrict__ x,
                                                    const float* __restrict__ g,
                                                    const float* __restrict__ be)
{
    int row = blockIdx.x;            // 0..8191
    const float4* base = (const float4*)(x + (size_t)row * CK);
    const float4* g4   = (const float4*)g;
    const float4* be4  = (const float4*)be;

    __shared__ float4 sbuf[CK / 4];  // 480
    __shared__ float red[256];
    int tid = threadIdx.x;

    float s = 0.f;
    for (int c = tid; c < CK / 4; c += 256) {
        float4 v = base[c];
        sbuf[c] = v;
        s += v.x + v.y + v.z + v.w;
    }
    red[tid] = s; __syncthreads();
    for (int st = 128; st > 0; st >>= 1) { if (tid < st) red[tid] += red[tid + st]; __syncthreads(); }
    float mu = red[0] * (1.f / CK);
    __syncthreads();

    float s2 = 0.f;
    for (int c = tid; c < CK / 4; c += 256) {
        float4 v = sbuf[c];
        float dx = v.x - mu, dy = v.y - mu, dz = v.z - mu, dw = v.w - mu;
        s2 += dx * dx + dy * dy + dz * dz + dw * dw;
    }
    red[tid] = s2; __syncthreads();
    for (int st = 128; st > 0; st >>= 1) { if (tid < st) red[tid] += red[tid + st]; __syncthreads(); }
    float rstd = rsqrtf(red[0] * (1.f / CK) + 1e-5f);

    float4* out = (float4*)(g_xkv + (size_t)row * CK);
    for (int c = tid; c < CK / 4; c += 256) {
        float4 v = sbuf[c], gv = g4[c], bv = be4[c];
        float4 o;
        o.x = (v.x - mu) * rstd * gv.x + bv.x;
        o.y = (v.y - mu) * rstd * gv.y + bv.y;
        o.z = (v.z - mu) * rstd * gv.z + bv.z;
        o.w = (v.w - mu) * rstd * gv.w + bv.w;
        out[c] = o;
    }
}

// ---------------- SGEMM: 128x128x16 tile, double-buffered, ffma2, 2 CTAs/SM ----------------
__global__ __launch_bounds__(256, 2) void gemm128(const float* __restrict__ A, int lda,
                                                  const float* __restrict__ Bw, int ldb,
                                                  const float* __restrict__ bias,
                                                  float* __restrict__ C, int ldc,
                                                  int K, int outMode)
{
    __shared__ float As[2][16][128];
    __shared__ float Bs[2][16][128];

    int tid = threadIdx.x;
    int bm = blockIdx.y * 128;
    int bn = blockIdx.x * 128;
    int tx = tid & 15, ty = tid >> 4;

    int ar = tid >> 1;            // 0..127
    int ac = (tid & 1) * 8;       // 0 or 8
    int br = tid >> 4;            // 0..15
    int bc = (tid & 15) * 4;      // 0..60

    const float* Ap = A + (size_t)(bm + ar) * lda + ac;
    const float* Bp = Bw + (size_t)br * ldb + bn + bc;

    ull acc[8][4];
#pragma unroll
    for (int i = 0; i < 8; i++)
#pragma unroll
        for (int j = 0; j < 4; j++) acc[i][j] = 0ULL;

    int nt = K >> 4;

    float4 av0 = *(const float4*)(Ap);
    float4 av1 = *(const float4*)(Ap + 4);
    float4 bv0 = *(const float4*)(Bp);
    float4 bv1 = *(const float4*)(Bp + 64);
    As[0][ac + 0][ar] = av0.x; As[0][ac + 1][ar] = av0.y;
    As[0][ac + 2][ar] = av0.z; As[0][ac + 3][ar] = av0.w;
    As[0][ac + 4][ar] = av1.x; As[0][ac + 5][ar] = av1.y;
    As[0][ac + 6][ar] = av1.z; As[0][ac + 7][ar] = av1.w;
    *(float4*)&Bs[0][br][bc]      = bv0;
    *(float4*)&Bs[0][br][bc + 64] = bv1;
    __syncthreads();

    for (int t = 0; t < nt; t++) {
        int cur = t & 1;
        if (t + 1 < nt) {
            const float* Ap2 = Ap + (t + 1) * 16;
            const float* Bp2 = Bp + (size_t)(t + 1) * 16 * ldb;
            av0 = *(const float4*)(Ap2);
            av1 = *(const float4*)(Ap2 + 4);
            bv0 = *(const float4*)(Bp2);
            bv1 = *(const float4*)(Bp2 + 64);
        }

#pragma unroll
        for (int kk = 0; kk < 16; kk++) {
            float4 a0 = *(const float4*)&As[cur][kk][ty * 4];
            float4 a1 = *(const float4*)&As[cur][kk][64 + ty * 4];
            float4 b0 = *(const float4*)&Bs[cur][kk][tx * 4];
            float4 b1 = *(const float4*)&Bs[cur][kk][64 + tx * 4];
            ull bd0 = pack2(b0.x, b0.y), bd1 = pack2(b0.z, b0.w);
            ull bd2 = pack2(b1.x, b1.y), bd3 = pack2(b1.z, b1.w);
            ull ad[8] = { dup2(a0.x), dup2(a0.y), dup2(a0.z), dup2(a0.w),
                          dup2(a1.x), dup2(a1.y), dup2(a1.z), dup2(a1.w) };
#pragma unroll
            for (int i = 0; i < 8; i++) {
                ffma2(acc[i][0], ad[i], bd0);
                ffma2(acc[i][1], ad[i], bd1);
                ffma2(acc[i][2], ad[i], bd2);
                ffma2(acc[i][3], ad[i], bd3);
            }
        }

        if (t + 1 < nt) {
            int nxt = cur ^ 1;
            As[nxt][ac + 0][ar] = av0.x; As[nxt][ac + 1][ar] = av0.y;
            As[nxt][ac + 2][ar] = av0.z; As[nxt][ac + 3][ar] = av0.w;
            As[nxt][ac + 4][ar] = av1.x; As[nxt][ac + 5][ar] = av1.y;
            As[nxt][ac + 6][ar] = av1.z; As[nxt][ac + 7][ar] = av1.w;
            *(float4*)&Bs[nxt][br][bc]      = bv0;
            *(float4*)&Bs[nxt][br][bc + 64] = bv1;
        }
        __syncthreads();
    }

    int n0 = bn + tx * 4;
    float4 bb0 = *(const float4*)&bias[n0];
    float4 bb1 = *(const float4*)&bias[n0 + 64];
#pragma unroll
    for (int i = 0; i < 8; i++) {
        int m = bm + ((i < 4) ? (ty * 4 + i) : (64 + ty * 4 + (i - 4)));
        float2 p0 = unpack2(acc[i][0]), p1 = unpack2(acc[i][1]);
        float2 p2 = unpack2(acc[i][2]), p3 = unpack2(acc[i][3]);
        float4 o0 = make_float4(p0.x + bb0.x, p0.y + bb0.y, p1.x + bb0.z, p1.y + bb0.w);
        float4 o1 = make_float4(p2.x + bb1.x, p2.y + bb1.y, p3.x + bb1.z, p3.y + bb1.w);
        if (outMode == 0) {
            *(float4*)&C[(size_t)m * ldc + n0]      = o0;
            *(float4*)&C[(size_t)m * ldc + n0 + 64] = o1;
        } else {
            int b   = m >> 10;
            int pix = m & 1023;
            size_t base = (size_t)b * DQ * HWN + pix;
            C[base + (size_t)(n0 + 0) * HWN] = o0.x;
            C[base + (size_t)(n0 + 1) * HWN] = o0.y;
            C[base + (size_t)(n0 + 2) * HWN] = o0.z;
            C[base + (size_t)(n0 + 3) * HWN] = o0.w;
            C[base + (size_t)(n0 + 64) * HWN] = o1.x;
            C[base + (size_t)(n0 + 65) * HWN] = o1.y;
            C[base + (size_t)(n0 + 66) * HWN] = o1.z;
            C[base + (size_t)(n0 + 67) * HWN] = o1.w;
        }
    }
}

// ---------------- Fused flash attention: S=QK^T, online softmax, O=PV ----------------
// grid (HW/64, B*NH), 256 threads. Per block: 64 query rows, full K sweep in 64-key tiles.
// No score tensor in HBM. Temporal weight constant per 64-key tile (1024 keys/frame).
#define LD   68   // smem row pitch (floats)
__global__ __launch_bounds__(256, 2) void flash_kernel(const float* __restrict__ tw)
{
    extern __shared__ float sm[];
    float* Qs = sm;                  // [64][LD]
    float* Ks = sm + 64 * LD;        // [64][LD]
    float* Vs = sm + 2 * 64 * LD;    // [64][LD]
    float* Ps = sm + 3 * 64 * LD;    // [64][LD]

    int bh = blockIdx.y;
    int b  = bh / NH;
    int h  = bh % NH;
    int qm0 = blockIdx.x * 64;

    int tid = threadIdx.x;
    int tx = tid & 15, ty = tid >> 4;

    // Load Q tile (64 rows x 64 dims of head h)
    {
        int r  = tid >> 2;            // 0..63
        int c0 = (tid & 3) * 16;      // 0,16,32,48
        const float* qsrc = g_q + (size_t)(b * HWN + qm0 + r) * DQ + h * HD + c0;
#pragma unroll
        for (int j = 0; j < 4; j++)
            *(float4*)&Qs[r * LD + c0 + 4 * j] = *(const float4*)(qsrc + 4 * j);
    }

    ull   o_acc[4][2];
    float m_i[4], l_i[4];
#pragma unroll
    for (int i = 0; i < 4; i++) {
        o_acc[i][0] = 0ULL; o_acc[i][1] = 0ULL;
        m_i[i] = -1e30f; l_i[i] = 0.f;
    }

    const float* kbase = g_k + (size_t)b * TKV * DQ + h * HD;
    const float* vbase = g_v + (size_t)b * TKV * DQ + h * HD;

    for (int kt = 0; kt < TKV / 64; kt++) {
        int kn0 = kt * 64;
        // Load K,V tiles (64 keys x 64 dims)
        {
            int r  = tid >> 2;
            int c0 = (tid & 3) * 16;
            const float* ksrc = kbase + (size_t)(kn0 + r) * DQ + c0;
            const float* vsrc = vbase + (size_t)(kn0 + r) * DQ + c0;
#pragma unroll
            for (int j = 0; j < 4; j++) {
                *(float4*)&Ks[r * LD + c0 + 4 * j] = *(const float4*)(ksrc + 4 * j);
                *(float4*)&Vs[r * LD + c0 + 4 * j] = *(const float4*)(vsrc + 4 * j);
            }
        }
        __syncthreads();

        // ---- S = Q K^T (4x4 per thread), packed over d pairs ----
        ull sacc[4][4];
#pragma unroll
        for (int i = 0; i < 4; i++)
#pragma unroll
            for (int j = 0; j < 4; j++) sacc[i][j] = 0ULL;

#pragma unroll 4
        for (int k4 = 0; k4 < 64; k4 += 4) {
            ull a2[4][2], b2[4][2];
#pragma unroll
            for (int i = 0; i < 4; i++) {
                float4 q = *(const float4*)&Qs[(ty * 4 + i) * LD + k4];
                a2[i][0] = pack2(q.x, q.y);
                a2[i][1] = pack2(q.z, q.w);
            }
#pragma unroll
            for (int j = 0; j < 4; j++) {
                float4 kv = *(const float4*)&Ks[(tx * 4 + j) * LD + k4];
                b2[j][0] = pack2(kv.x, kv.y);
                b2[j][1] = pack2(kv.z, kv.w);
            }
#pragma unroll
            for (int i = 0; i < 4; i++)
#pragma unroll
                for (int j = 0; j < 4; j++) {
                    ffma2(sacc[i][j], a2[i][0], b2[j][0]);
                    ffma2(sacc[i][j], a2[i][1], b2[j][1]);
                }
        }

        float scale = 0.125f * tw[kn0 >> 10];
        float s[4][4];
#pragma unroll
        for (int i = 0; i < 4; i++)
#pragma unroll
            for (int j = 0; j < 4; j++) {
                float2 p = unpack2(sacc[i][j]);
                s[i][j] = (p.x + p.y) * scale;
            }

        // ---- online softmax: row stats over 16 tx lanes ----
#pragma unroll
        for (int i = 0; i < 4; i++) {
            float mt = fmaxf(fmaxf(s[i][0], s[i][1]), fmaxf(s[i][2], s[i][3]));
#pragma unroll
            for (int m = 1; m < 16; m <<= 1)
                mt = fmaxf(mt, __shfl_xor_sync(0xffffffffu, mt, m));
            float m_new = fmaxf(m_i[i], mt);
            float corr  = __expf(m_i[i] - m_new);
            float rs = 0.f;
#pragma unroll
            for (int j = 0; j < 4; j++) {
                float p = __expf(s[i][j] - m_new);
                s[i][j] = p;
                rs += p;
            }
#pragma unroll
            for (int m = 1; m < 16; m <<= 1)
                rs += __shfl_xor_sync(0xffffffffu, rs, m);
            l_i[i] = l_i[i] * corr + rs;
            m_i[i] = m_new;
            ull cc = dup2(corr);
            mul2(o_acc[i][0], cc);
            mul2(o_acc[i][1], cc);
        }

        // ---- stage P, then O += P V ----
#pragma unroll
        for (int i = 0; i < 4; i++)
            *(float4*)&Ps[(ty * 4 + i) * LD + tx * 4] =
                make_float4(s[i][0], s[i][1], s[i][2], s[i][3]);
        __syncthreads();

#pragma unroll 4
        for (int kk = 0; kk < 64; kk++) {
            float4 vr = *(const float4*)&Vs[kk * LD + tx * 4];
            ull b0 = pack2(vr.x, vr.y), b1 = pack2(vr.z, vr.w);
#pragma unroll
            for (int i = 0; i < 4; i++) {
                ull a = dup2(Ps[(ty * 4 + i) * LD + kk]);
                ffma2(o_acc[i][0], a, b0);
                ffma2(o_acc[i][1], a, b1);
            }
        }
        __syncthreads();
    }

    // ---- epilogue: O / l ----
#pragma unroll
    for (int i = 0; i < 4; i++) {
        float inv = 1.f / l_i[i];
        float2 r0 = unpack2(o_acc[i][0]), r1 = unpack2(o_acc[i][1]);
        float4 o = make_float4(r0.x * inv, r0.y * inv, r1.x * inv, r1.y * inv);
        *(float4*)&g_att[((size_t)(b * HWN + qm0 + ty * 4 + i)) * DQ + h * HD + tx * 4] = o;
    }
}

#define FLASH_SMEM (4 * 64 * LD * 4)   // 69,632 bytes

// ---------------- Launch ----------------
extern "C" void kernel_launch(void* const* d_in, const int* in_sizes, int n_in,
                              void* d_out, int out_size)
{
    const float* dino = (const float*)d_in[0];
    const float* cog  = (const float*)d_in[1];
    const float* tw   = (const float*)d_in[2];
    const float* Wq   = (const float*)d_in[3];
    const float* bq   = (const float*)d_in[4];
    const float* Wk   = (const float*)d_in[5];
    const float* bk   = (const float*)d_in[6];
    const float* Wv   = (const float*)d_in[7];
    const float* bv   = (const float*)d_in[8];
    const float* Wo   = (const float*)d_in[9];
    const float* bo   = (const float*)d_in[10];
    const float* gq   = (const float*)d_in[11];
    const float* Bq   = (const float*)d_in[12];
    const float* gkv  = (const float*)d_in[13];
    const float* Bkv  = (const float*)d_in[14];
    float* out = (float*)d_out;

    float *p_xq, *p_xkv, *p_q, *p_k, *p_v, *p_att;
    cudaGetSymbolAddress((void**)&p_xq,  g_xq);
    cudaGetSymbolAddress((void**)&p_xkv, g_xkv);
    cudaGetSymbolAddress((void**)&p_q,   g_q);
    cudaGetSymbolAddress((void**)&p_k,   g_k);
    cudaGetSymbolAddress((void**)&p_v,   g_v);
    cudaGetSymbolAddress((void**)&p_att, g_att);

    cudaFuncSetAttribute(flash_kernel, cudaFuncAttributeMaxDynamicSharedMemorySize, FLASH_SMEM);

    // 1. LayerNorms
    ln_q_kernel <<<MQ,  256>>>(dino, gq,  Bq);
    ln_kv_kernel<<<MKV, 256>>>(cog,  gkv, Bkv);

    // 2. Projections
    gemm128<<<dim3(DQ/128, MQ/128),  256>>>(p_xq,  DQ, Wq, DQ, bq, p_q, DQ, DQ, 0);
    gemm128<<<dim3(DQ/128, MKV/128), 256>>>(p_xkv, CK, Wk, DQ, bk, p_k, DQ, CK, 0);
    gemm128<<<dim3(DQ/128, MKV/128), 256>>>(p_xkv, CK, Wv, DQ, bv, p_v, DQ, CK, 0);

    // 3. Fused attention (scores + softmax + PV)
    flash_kernel<<<dim3(HWN/64, BB*NH), 256, FLASH_SMEM>>>(tw);

    // 4. Output projection with fused BCHW transpose
    gemm128<<<dim3(DQ/128, MQ/128), 256>>>(p_att, DQ, Wo, DQ, bo, out, DQ, DQ, 1);
}